// round 16
// baseline (speedup 1.0000x reference)
#include <cuda_runtime.h>
#include <cuda_bf16.h>
#include <math.h>
#include <stdint.h>

// ---------------------------------------------------------------------------
// Net_23553600651528: [conv1 fused into conv2 block] -> conv2 (bf16 mma,
// TWO batch elements per block sharing B fragments, B double-buffered) +
// relu + maxpool (bf16) -> fc1 (bf16 mma, K-split 16, M/N-split warps,
// A prefetch) -> [reduce fused into qsim; Clifford folded analytically;
// fc2+sigmoid -> <Y> -> log_softmax].  B = 2048.
// ---------------------------------------------------------------------------

#define BATCH 2048

// scratch (__device__ globals; allocation-free rule)
__device__ __nv_bfloat16 g_poolh[BATCH * 9216]; // pooled conv2 bf16, [b][quad*64+oc]
__device__ float g_part[16 * BATCH * 128];      // fc1 K-split partials
__device__ uint4 g_wfragb[18 * 4 * 32];         // conv2 weights, bf16 B-fragments
__device__ uint4 g_fc1wfrag[576 * 8 * 32];      // fc1 weights, bf16 B-fragments

__device__ __forceinline__ uint32_t packbf(float lo, float hi) {
    __nv_bfloat162 h2 = __floats2bfloat162_rn(lo, hi);   // .x=lo -> low 16 bits
    return *reinterpret_cast<uint32_t*>(&h2);
}

__device__ __forceinline__ void mma_bf16(float& c0, float& c1, float& c2, float& c3,
                                         uint32_t a0, uint32_t a1, uint32_t a2, uint32_t a3,
                                         uint32_t b0, uint32_t b1) {
    asm volatile("mma.sync.aligned.m16n8k16.row.col.f32.bf16.bf16.f32 "
                 "{%0,%1,%2,%3}, {%4,%5,%6,%7}, {%8,%9}, {%0,%1,%2,%3};"
                 : "+f"(c0), "+f"(c1), "+f"(c2), "+f"(c3)
                 : "r"(a0), "r"(a1), "r"(a2), "r"(a3), "r"(b0), "r"(b1));
}

// ---------------------------------------------------------------------------
// prep: conv2 weights -> bf16 B-fragments (m16n8k16).
// ---------------------------------------------------------------------------
__global__ void prep_wfrag_kernel(const float* __restrict__ w2)
{
    const int s = blockIdx.x;          // 0..17
    const int tid = threadIdx.x;       // 0..127
    const int p = tid >> 5;
    const int lane = tid & 31;
    const int g = lane >> 2, c = lane & 3;
    const int r = s >> 1;
    const int icb = (s & 1) * 16;
    const int oc_a = (2 * p) * 8 + g;
    const int oc_b = oc_a + 8;
    const int i00 = icb + 2 * c, i01 = i00 + 1;
    const int i10 = i00 + 8,     i11 = i10 + 1;
#define WV(ic, oc) w2[(oc) * 288 + (ic) * 9 + r]
    uint4 v;
    v.x = packbf(WV(i00, oc_a), WV(i01, oc_a));
    v.y = packbf(WV(i10, oc_a), WV(i11, oc_a));
    v.z = packbf(WV(i00, oc_b), WV(i01, oc_b));
    v.w = packbf(WV(i10, oc_b), WV(i11, oc_b));
#undef WV
    g_wfragb[(s * 4 + p) * 32 + lane] = v;
}

// ---------------------------------------------------------------------------
// prep: fc1 weights -> bf16 B-fragments DIRECTLY from fc1_w.
// k' = quad*64 + oc; for k-step s: quad = s>>2, oc = (s&3)*16 + j.
// ---------------------------------------------------------------------------
__global__ void prep_fc1frag_kernel(const float* __restrict__ fc1_w)
{
    const int s = blockIdx.x;          // 0..575
    const int tid = threadIdx.x;       // 0..255
    const int p = tid >> 5;            // n-frag pair 0..7
    const int lane = tid & 31;
    const int g = lane >> 2, c = lane & 3;
    const int quad = s >> 2;
    const int ocb = (s & 3) * 16;
    const int n_a = (2 * p) * 8 + g;
    const int n_b = n_a + 8;
    const float* Wa = fc1_w + (size_t)n_a * 9216 + quad;
    const float* Wb = fc1_w + (size_t)n_b * 9216 + quad;
#define WJ(W, j) (W)[(ocb + (j)) * 144]
    uint4 v;
    v.x = packbf(WJ(Wa, 2 * c),     WJ(Wa, 2 * c + 1));
    v.y = packbf(WJ(Wa, 2 * c + 8), WJ(Wa, 2 * c + 9));
    v.z = packbf(WJ(Wb, 2 * c),     WJ(Wb, 2 * c + 1));
    v.w = packbf(WJ(Wb, 2 * c + 8), WJ(Wb, 2 * c + 9));
#undef WJ
    g_fc1wfrag[(s * 8 + p) * 32 + lane] = v;
}

// ---------------------------------------------------------------------------
// fused conv1+conv2, TWO batch elements per block (r11/r12 winner, unchanged).
// ---------------------------------------------------------------------------
__global__ void __launch_bounds__(256, 2) conv12_kernel(const float* __restrict__ x,
                                                        const float* __restrict__ w1,
                                                        const float* __restrict__ b1,
                                                        const float* __restrict__ b2)
{
    extern __shared__ char smem[];
    uint32_t* sIn0 = (uint32_t*)smem;
    uint32_t* sIn1 = (uint32_t*)(smem + 45968);
    float* sx0 = (float*)(smem + 91936);
    float* sx1 = (float*)(smem + 91936 + 3136);
    float* sw1 = (float*)(smem + 91936 + 6272);
    float* sb1 = (float*)(smem + 91936 + 6272 + 1152);
    float* sb2 = (float*)(smem + 91936 + 6272 + 1152 + 128);

    const int b0 = blockIdx.x * 2;
    const int tid = threadIdx.x;
    const int w = tid >> 5;
    const int lane = tid & 31;

    for (int i = tid; i < 784; i += 256) {
        sx0[i] = x[b0 * 784 + i];
        sx1[i] = x[(b0 + 1) * 784 + i];
    }
    for (int i = tid; i < 288; i += 256) sw1[i] = w1[i];
    if (tid < 32) sb1[tid] = b1[tid];
    for (int i = tid; i < 64; i += 256) sb2[i] = b2[i];
    __syncthreads();

    for (int pp = tid; pp < 1352; pp += 256) {
        const int bb = (pp >= 676);
        const int p = pp - (bb ? 676 : 0);
        const float* sx = bb ? sx1 : sx0;
        uint32_t* dst = (bb ? sIn1 : sIn0) + p * 17;
        const int oy = p / 26, ox = p % 26;
        float in[9];
#pragma unroll
        for (int kh = 0; kh < 3; kh++)
#pragma unroll
            for (int kw = 0; kw < 3; kw++)
                in[kh * 3 + kw] = sx[(oy + kh) * 28 + ox + kw];
#pragma unroll 4
        for (int oc2 = 0; oc2 < 16; oc2++) {
            float va = sb1[2 * oc2], vb = sb1[2 * oc2 + 1];
            const float* wa = sw1 + (2 * oc2) * 9;
#pragma unroll
            for (int j = 0; j < 9; j++) { va += wa[j] * in[j]; vb += wa[9 + j] * in[j]; }
            dst[oc2] = packbf(fmaxf(va, 0.0f), fmaxf(vb, 0.0f));
        }
    }
    __syncthreads();

    const int c = lane & 3;
    const int rl0 = lane >> 2;
    __nv_bfloat16* outB0 = g_poolh + (size_t)b0 * 9216;
    __nv_bfloat16* outB1 = g_poolh + (size_t)(b0 + 1) * 9216;

    for (int t = 0; t < 5; t++) {
        if (t == 4 && w >= 4) break;
        int off0, off1;
        {
            const int qb = t * 32 + w * 4;
            int rl = rl0;
            int quad = qb + (rl >> 2), e = rl & 3;
            int qy = quad / 12, qx = quad - qy * 12;
            off0 = (2 * qy + (e >> 1)) * 26 + 2 * qx + (e & 1);
            rl = rl0 + 8;
            quad = qb + (rl >> 2); e = rl & 3;
            qy = quad / 12; qx = quad - qy * 12;
            off1 = (2 * qy + (e >> 1)) * 26 + 2 * qx + (e & 1);
        }
        const int w0 = off0 * 17 + c;
        const int w1b = off1 * 17 + c;

        float accA[8][4], accE[8][4];
#pragma unroll
        for (int n = 0; n < 8; n++) {
            accA[n][0] = 0.f; accA[n][1] = 0.f; accA[n][2] = 0.f; accA[n][3] = 0.f;
            accE[n][0] = 0.f; accE[n][1] = 0.f; accE[n][2] = 0.f; accE[n][3] = 0.f;
        }

        uint4 bqn[4];
#pragma unroll
        for (int p4 = 0; p4 < 4; p4++) bqn[p4] = g_wfragb[p4 * 32 + lane];

#pragma unroll
        for (int s = 0; s < 18; s++) {
            const int r = s >> 1;
            const int base = ((r / 3) * 26 + (r % 3)) * 17 + (s & 1) * 8;

            uint4 bq[4];
#pragma unroll
            for (int p4 = 0; p4 < 4; p4++) bq[p4] = bqn[p4];
            if (s < 17) {
                const uint4* wfn = g_wfragb + (s + 1) * 128;
#pragma unroll
                for (int p4 = 0; p4 < 4; p4++) bqn[p4] = wfn[p4 * 32 + lane];
            }

            const uint32_t a0 = sIn0[w0 + base];
            const uint32_t a1 = sIn0[w1b + base];
            const uint32_t a2 = sIn0[w0 + base + 4];
            const uint32_t a3 = sIn0[w1b + base + 4];
            const uint32_t e0 = sIn1[w0 + base];
            const uint32_t e1 = sIn1[w1b + base];
            const uint32_t e2 = sIn1[w0 + base + 4];
            const uint32_t e3 = sIn1[w1b + base + 4];

#pragma unroll
            for (int p4 = 0; p4 < 4; p4++) {
                mma_bf16(accA[2 * p4][0], accA[2 * p4][1], accA[2 * p4][2], accA[2 * p4][3],
                         a0, a1, a2, a3, bq[p4].x, bq[p4].y);
                mma_bf16(accA[2 * p4 + 1][0], accA[2 * p4 + 1][1],
                         accA[2 * p4 + 1][2], accA[2 * p4 + 1][3],
                         a0, a1, a2, a3, bq[p4].z, bq[p4].w);
                mma_bf16(accE[2 * p4][0], accE[2 * p4][1], accE[2 * p4][2], accE[2 * p4][3],
                         e0, e1, e2, e3, bq[p4].x, bq[p4].y);
                mma_bf16(accE[2 * p4 + 1][0], accE[2 * p4 + 1][1],
                         accE[2 * p4 + 1][2], accE[2 * p4 + 1][3],
                         e0, e1, e2, e3, bq[p4].z, bq[p4].w);
            }
        }

        const int hh = lane >> 4;
        const int rp = lane & 3;
        const bool writer = ((lane & 12) == 0);
        const int qb = t * 32 + w * 4;
#pragma unroll
        for (int f = 0; f < 2; f++) {
            __nv_bfloat16* outB = f ? outB1 : outB0;
#pragma unroll
            for (int n = 0; n < 8; n++) {
                float v0 = f ? accE[n][0] : accA[n][0];
                float v1 = f ? accE[n][1] : accA[n][1];
                float v2 = f ? accE[n][2] : accA[n][2];
                float v3 = f ? accE[n][3] : accA[n][3];
#pragma unroll
                for (int d = 4; d <= 8; d <<= 1) {
                    v0 = fmaxf(v0, __shfl_xor_sync(0xffffffffu, v0, d));
                    v1 = fmaxf(v1, __shfl_xor_sync(0xffffffffu, v1, d));
                    v2 = fmaxf(v2, __shfl_xor_sync(0xffffffffu, v2, d));
                    v3 = fmaxf(v3, __shfl_xor_sync(0xffffffffu, v3, d));
                }
                if (writer) {
                    const int oc = n * 8 + 2 * rp;
                    const float ba = sb2[oc], bb = sb2[oc + 1];
                    *(uint32_t*)(outB + (qb + hh) * 64 + oc) =
                        packbf(fmaxf(v0 + ba, 0.f), fmaxf(v1 + bb, 0.f));
                    *(uint32_t*)(outB + (qb + 2 + hh) * 64 + oc) =
                        packbf(fmaxf(v2 + ba, 0.f), fmaxf(v3 + bb, 0.f));
                }
            }
        }
    }
}

// ---------------------------------------------------------------------------
// fc1 bf16 tensor-core, K-split 16, M/N-split warps:
// grid (32 Mblocks of 64 rows, 16 ksplits) = 512 blocks.
// Warp w: rows (w&3)*16, n-frags (w>>2)*8 .. +7.  A words shared between
// the two warps of a row-group (second hit is L1).  A prefetched 1 step.
// ---------------------------------------------------------------------------
__global__ void __launch_bounds__(256) fc1_part_kernel()
{
    const int tid = threadIdx.x;
    const int w = tid >> 5;
    const int lane = tid & 31;
    const int Mb = blockIdx.x;         // 0..31 (64 rows each)
    const int ks = blockIdx.y;         // 0..15
    const int m0 = Mb * 64 + (w & 3) * 16;
    const int nh = w >> 2;             // n-half 0/1
    const int g = lane >> 2, c = lane & 3;

    float acc[8][4];
#pragma unroll
    for (int f = 0; f < 8; f++) {
        acc[f][0] = 0.f; acc[f][1] = 0.f; acc[f][2] = 0.f; acc[f][3] = 0.f;
    }

    const __nv_bfloat16* A0 = g_poolh + (size_t)(m0 + g) * 9216 + ks * 576 + 2 * c;
    const __nv_bfloat16* A1 = g_poolh + (size_t)(m0 + g + 8) * 9216 + ks * 576 + 2 * c;

    uint32_t a0 = *(const uint32_t*)(A0);
    uint32_t a1 = *(const uint32_t*)(A1);
    uint32_t a2 = *(const uint32_t*)(A0 + 8);
    uint32_t a3 = *(const uint32_t*)(A1 + 8);

#pragma unroll 2
    for (int step = 0; step < 36; step++) {
        uint32_t n0 = 0, n1 = 0, n2 = 0, n3 = 0;
        if (step < 35) {
            const int kn = (step + 1) * 16;
            n0 = *(const uint32_t*)(A0 + kn);
            n1 = *(const uint32_t*)(A1 + kn);
            n2 = *(const uint32_t*)(A0 + kn + 8);
            n3 = *(const uint32_t*)(A1 + kn + 8);
        }
        const uint4* wf = g_fc1wfrag + (size_t)(ks * 36 + step) * 256 + nh * 128;
#pragma unroll
        for (int p4 = 0; p4 < 4; p4++) {
            const uint4 bq = wf[p4 * 32 + lane];
            mma_bf16(acc[2 * p4][0], acc[2 * p4][1], acc[2 * p4][2], acc[2 * p4][3],
                     a0, a1, a2, a3, bq.x, bq.y);
            mma_bf16(acc[2 * p4 + 1][0], acc[2 * p4 + 1][1],
                     acc[2 * p4 + 1][2], acc[2 * p4 + 1][3],
                     a0, a1, a2, a3, bq.z, bq.w);
        }
        a0 = n0; a1 = n1; a2 = n2; a3 = n3;
    }

    float* dst = g_part + (size_t)ks * BATCH * 128;
#pragma unroll
    for (int f = 0; f < 8; f++) {
        const int n0i = (nh * 8 + f) * 8 + 2 * c;
        *(float2*)(dst + (size_t)(m0 + g) * 128 + n0i) = make_float2(acc[f][0], acc[f][1]);
        *(float2*)(dst + (size_t)(m0 + g + 8) * 128 + n0i) = make_float2(acc[f][2], acc[f][3]);
    }
}

// ---------------------------------------------------------------------------
// quantum kernel; wire w <-> bit (9-w).  (r12/r13 version; reduce loop 16.)
// ---------------------------------------------------------------------------
__device__ __forceinline__ float2 cmul(float2 a, float2 b) {
    return make_float2(a.x * b.x - a.y * b.y, a.x * b.y + a.y * b.x);
}
__device__ __forceinline__ float2 cadd(float2 a, float2 b) {
    return make_float2(a.x + b.x, a.y + b.y);
}

__global__ void qsim_kernel(const float* __restrict__ fc1b,
                            const float* __restrict__ fc2w,
                            const float* __restrict__ fc2b,
                            const float* __restrict__ theta0,
                            const float* __restrict__ theta_rz,
                            const float* __restrict__ theta_ps,
                            const float* __restrict__ rot_p,
                            float* __restrict__ out)
{
    __shared__ float sh[128];
    __shared__ float sang[10];
    __shared__ float2 svec[10][2];
    __shared__ float2 psi[1024];
    __shared__ float sredk[8][10];
    __shared__ float sev[10];

    const int b = blockIdx.x;
    const int tid = threadIdx.x;
    const int wid = tid >> 5, lane = tid & 31;

    // fc1 K-split reduce + bias + relu
    if (tid < 128) {
        float s = 0.0f;
#pragma unroll
        for (int ks = 0; ks < 16; ks++)
            s += g_part[(size_t)ks * BATCH * 128 + (size_t)b * 128 + tid];
        sh[tid] = fmaxf(s + fc1b[tid], 0.0f);
    }
    __syncthreads();

    if (tid < 10) {
        float z = fc2b[tid];
        const float4* sh4 = (const float4*)sh;
        const float4* wr4 = (const float4*)(fc2w + tid * 128);
        for (int k = 0; k < 32; k++) {
            const float4 hv = sh4[k], wv = wr4[k];
            z += hv.x * wv.x + hv.y * wv.y + hv.z * wv.z + hv.w * wv.w;
        }
        const float a = 6.2831853071795864f / (1.0f + expf(-z));
        sang[tid] = a;

        float alpha = theta0[tid] + a;
        if (tid == 1) alpha += a;
        if (tid == 5) alpha -= 0.78539816339745f;
        const float c = cosf(0.5f * alpha);
        const float s = sinf(0.5f * alpha);
        float2 v0 = make_float2(c, 0.0f);
        float2 v1 = make_float2(0.0f, -s);

        if (tid == 2) {
            const float cy = cosf(0.5f * a), sy = sinf(0.5f * a);
            v0 = make_float2(cy * c, sy * s);
            v1 = make_float2(sy * c, -cy * s);
        } else if (tid == 3) {
            const float2 e = make_float2(cosf(0.5f * a), -sinf(0.5f * a));
            v0 = cmul(v0, e);
            v1 = cmul(v1, make_float2(e.x, -e.y));
        } else if (tid == 4) {
            v1 = make_float2(s, 0.0f);
        } else if (tid == 5) {
            const float r = 0.70710678118654752f;
            v1 = make_float2(s * r, -s * r);
        } else if (tid == 6) {
            const float t = theta_rz[0];
            const float2 e = make_float2(cosf(0.5f * t), -sinf(0.5f * t));
            v0 = cmul(v0, e);
            v1 = cmul(v1, make_float2(e.x, -e.y));
        } else if (tid == 7) {
            const float h0 = 0.5f * (c - s), h1 = 0.5f * (c + s);
            v0 = make_float2(h0, h0);
            v1 = make_float2(h1, -h1);
        }
        svec[tid][0] = v0;
        svec[tid][1] = v1;
    }
    __syncthreads();

    // ---- init with analytic gather of the whole Clifford/phase segment ----
    {
        const float tps = theta_ps[0];
        const float a7 = sang[7];
        const float2 e8 = make_float2(cosf(tps), sinf(tps));
        const float2 e7 = make_float2(cosf(a7), sinf(a7));

#pragma unroll
        for (int ii = 0; ii < 4; ii++) {
            const int i = tid + ii * 256;
            int j = ((i & 18) == 18) ? (i ^ 512) : i;
            if ((j & 32) && (((j >> 3) ^ (j >> 4)) & 1)) j ^= 24;
            if (((j >> 7) ^ (j >> 6)) & 1) j ^= 192;
            const bool cy = (j & 64) != 0;
            const int src = cy ? (j ^ 2) : j;

            float2 p = svec[0][(src >> 9) & 1];
#pragma unroll
            for (int k = 1; k < 10; k++)
                p = cmul(p, svec[k][(src >> (9 - k)) & 1]);
            if (src & 512) p = make_float2(p.y, -p.x);
            if (cy) p = (j & 2) ? make_float2(-p.y, p.x) : make_float2(p.y, -p.x);
            if (i & 2) p = cmul(p, e8);
            if (i & 4) p = cmul(p, e7);
            psi[i] = p;
        }
    }
    __syncthreads();

    // ---- combined Rot(wire4, bit32) x Rot(wire5, bit16) ----
    {
        float m4c, m4s, m4hs, m4hd;
        {
            const float phi = rot_p[0], th = rot_p[1], om = rot_p[2];
            m4c = cosf(0.5f * th); m4s = sinf(0.5f * th);
            m4hs = 0.5f * (phi + om); m4hd = 0.5f * (phi - om);
        }
        const float2 A00 = make_float2(m4c * cosf(m4hs), -m4c * sinf(m4hs));
        const float2 A01 = make_float2(-m4s * cosf(m4hd), -m4s * sinf(m4hd));
        const float2 A10 = make_float2(m4s * cosf(m4hd), -m4s * sinf(m4hd));
        const float2 A11 = make_float2(m4c * cosf(m4hs), m4c * sinf(m4hs));
        float m5c, m5s, m5hs, m5hd;
        {
            const float phi = sang[6], th = sang[7], om = sang[8];
            m5c = cosf(0.5f * th); m5s = sinf(0.5f * th);
            m5hs = 0.5f * (phi + om); m5hd = 0.5f * (phi - om);
        }
        const float2 B00 = make_float2(m5c * cosf(m5hs), -m5c * sinf(m5hs));
        const float2 B01 = make_float2(-m5s * cosf(m5hd), -m5s * sinf(m5hd));
        const float2 B10 = make_float2(m5s * cosf(m5hd), -m5s * sinf(m5hd));
        const float2 B11 = make_float2(m5c * cosf(m5hs), m5c * sinf(m5hs));

        const int g0 = (tid & 15) | ((tid >> 4) << 6);
        float2 t00 = psi[g0];
        float2 t01 = psi[g0 | 32];
        float2 t10 = psi[g0 | 16];
        float2 t11 = psi[g0 | 48];

        float2 u00 = cadd(cmul(A00, t00), cmul(A01, t01));
        float2 u01 = cadd(cmul(A10, t00), cmul(A11, t01));
        float2 u10 = cadd(cmul(A00, t10), cmul(A01, t11));
        float2 u11 = cadd(cmul(A10, t10), cmul(A11, t11));
        psi[g0]      = cadd(cmul(B00, u00), cmul(B01, u10));
        psi[g0 | 32] = cadd(cmul(B00, u01), cmul(B01, u11));
        psi[g0 | 16] = cadd(cmul(B10, u00), cmul(B11, u10));
        psi[g0 | 48] = cadd(cmul(B10, u01), cmul(B11, u11));
    }
    __syncthreads();

    // ---- single-pass expectations ----
    float ev[10];
#pragma unroll
    for (int k = 0; k < 10; k++) ev[k] = 0.0f;
#pragma unroll
    for (int ii = 0; ii < 4; ii++) {
        const int i = tid + ii * 256;
        const float2 a0 = psi[i];
#pragma unroll
        for (int k = 0; k < 10; k++) {
            const int bit = 512 >> k;
            if (!(i & bit)) {
                const float2 a1 = psi[i | bit];
                ev[k] += a0.x * a1.y - a0.y * a1.x;
            }
        }
    }
#pragma unroll
    for (int k = 0; k < 10; k++) {
#pragma unroll
        for (int off = 16; off > 0; off >>= 1)
            ev[k] += __shfl_down_sync(0xffffffffu, ev[k], off);
    }
    if (lane == 0) {
#pragma unroll
        for (int k = 0; k < 10; k++) sredk[wid][k] = ev[k];
    }
    __syncthreads();
    if (tid < 10) {
        float s = 0.0f;
#pragma unroll
        for (int w = 0; w < 8; w++) s += sredk[w][tid];
        sev[tid] = 2.0f * s;
    }
    __syncthreads();

    if (tid == 0) {
        float m = sev[0];
#pragma unroll
        for (int k = 1; k < 10; k++) m = fmaxf(m, sev[k]);
        float ssum = 0.0f;
#pragma unroll
        for (int k = 0; k < 10; k++) ssum += expf(sev[k] - m);
        const float l = logf(ssum);
#pragma unroll
        for (int k = 0; k < 10; k++)
            out[(size_t)b * 10 + k] = sev[k] - m - l;
    }
}

// ---------------------------------------------------------------------------
// launch
// ---------------------------------------------------------------------------
extern "C" void kernel_launch(void* const* d_in, const int* in_sizes, int n_in,
                              void* d_out, int out_size)
{
    const float* x        = (const float*)d_in[0];
    const float* conv1_w  = (const float*)d_in[1];
    const float* conv1_b  = (const float*)d_in[2];
    const float* conv2_w  = (const float*)d_in[3];
    const float* conv2_b  = (const float*)d_in[4];
    const float* fc1_w    = (const float*)d_in[5];
    const float* fc1_b    = (const float*)d_in[6];
    const float* fc2_w    = (const float*)d_in[7];
    const float* fc2_b    = (const float*)d_in[8];
    const float* theta0   = (const float*)d_in[9];
    const float* theta_rz = (const float*)d_in[10];
    const float* theta_ps = (const float*)d_in[11];
    const float* rot_p    = (const float*)d_in[12];
    float* out = (float*)d_out;

    // 2*45968 + 2*3136 + 1152 + 128 + 256 = 99744 B
    const int conv_smem = 99744;
    cudaFuncSetAttribute(conv12_kernel, cudaFuncAttributeMaxDynamicSharedMemorySize,
                         conv_smem);

    prep_wfrag_kernel<<<18, 128>>>(conv2_w);
    prep_fc1frag_kernel<<<576, 256>>>(fc1_w);
    conv12_kernel<<<BATCH / 2, 256, conv_smem>>>(x, conv1_w, conv1_b, conv2_b);
    fc1_part_kernel<<<dim3(32, 16), 256>>>();
    qsim_kernel<<<BATCH, 256>>>(fc1_b, fc2_w, fc2_b, theta0, theta_rz, theta_ps, rot_p, out);
}

// round 17
// speedup vs baseline: 1.0509x; 1.0509x over previous
#include <cuda_runtime.h>
#include <cuda_bf16.h>
#include <math.h>
#include <stdint.h>

// ---------------------------------------------------------------------------
// Net_23553600651528: [conv1 fused into conv2 block] -> conv2 (bf16 mma,
// TWO batch elements per block sharing B fragments, B double-buffered) +
// relu + maxpool (bf16) -> fc1 (bf16 mma, K-split 16, A prefetch x2) ->
// [reduce fused into qsim; Clifford folded analytically; fc2+sigmoid ->
// <Y> -> log_softmax].  B = 2048.
// ---------------------------------------------------------------------------

#define BATCH 2048

// scratch (__device__ globals; allocation-free rule)
__device__ __nv_bfloat16 g_poolh[BATCH * 9216]; // pooled conv2 bf16, [b][quad*64+oc]
__device__ float g_part[16 * BATCH * 128];      // fc1 K-split partials
__device__ uint4 g_wfragb[18 * 4 * 32];         // conv2 weights, bf16 B-fragments
__device__ uint4 g_fc1wfrag[576 * 8 * 32];      // fc1 weights, bf16 B-fragments

__device__ __forceinline__ uint32_t packbf(float lo, float hi) {
    __nv_bfloat162 h2 = __floats2bfloat162_rn(lo, hi);   // .x=lo -> low 16 bits
    return *reinterpret_cast<uint32_t*>(&h2);
}

__device__ __forceinline__ void mma_bf16(float& c0, float& c1, float& c2, float& c3,
                                         uint32_t a0, uint32_t a1, uint32_t a2, uint32_t a3,
                                         uint32_t b0, uint32_t b1) {
    asm volatile("mma.sync.aligned.m16n8k16.row.col.f32.bf16.bf16.f32 "
                 "{%0,%1,%2,%3}, {%4,%5,%6,%7}, {%8,%9}, {%0,%1,%2,%3};"
                 : "+f"(c0), "+f"(c1), "+f"(c2), "+f"(c3)
                 : "r"(a0), "r"(a1), "r"(a2), "r"(a3), "r"(b0), "r"(b1));
}

// ---------------------------------------------------------------------------
// prep: conv2 weights -> bf16 B-fragments (m16n8k16).
// ---------------------------------------------------------------------------
__global__ void prep_wfrag_kernel(const float* __restrict__ w2)
{
    const int s = blockIdx.x;          // 0..17
    const int tid = threadIdx.x;       // 0..127
    const int p = tid >> 5;
    const int lane = tid & 31;
    const int g = lane >> 2, c = lane & 3;
    const int r = s >> 1;
    const int icb = (s & 1) * 16;
    const int oc_a = (2 * p) * 8 + g;
    const int oc_b = oc_a + 8;
    const int i00 = icb + 2 * c, i01 = i00 + 1;
    const int i10 = i00 + 8,     i11 = i10 + 1;
#define WV(ic, oc) w2[(oc) * 288 + (ic) * 9 + r]
    uint4 v;
    v.x = packbf(WV(i00, oc_a), WV(i01, oc_a));
    v.y = packbf(WV(i10, oc_a), WV(i11, oc_a));
    v.z = packbf(WV(i00, oc_b), WV(i01, oc_b));
    v.w = packbf(WV(i10, oc_b), WV(i11, oc_b));
#undef WV
    g_wfragb[(s * 4 + p) * 32 + lane] = v;
}

// ---------------------------------------------------------------------------
// prep: fc1 weights -> bf16 B-fragments DIRECTLY from fc1_w.
// k' = quad*64 + oc; for k-step s: quad = s>>2, oc = (s&3)*16 + j.
// ---------------------------------------------------------------------------
__global__ void prep_fc1frag_kernel(const float* __restrict__ fc1_w)
{
    const int s = blockIdx.x;          // 0..575
    const int tid = threadIdx.x;       // 0..255
    const int p = tid >> 5;            // n-frag pair 0..7
    const int lane = tid & 31;
    const int g = lane >> 2, c = lane & 3;
    const int quad = s >> 2;
    const int ocb = (s & 3) * 16;
    const int n_a = (2 * p) * 8 + g;
    const int n_b = n_a + 8;
    const float* Wa = fc1_w + (size_t)n_a * 9216 + quad;
    const float* Wb = fc1_w + (size_t)n_b * 9216 + quad;
#define WJ(W, j) (W)[(ocb + (j)) * 144]
    uint4 v;
    v.x = packbf(WJ(Wa, 2 * c),     WJ(Wa, 2 * c + 1));
    v.y = packbf(WJ(Wa, 2 * c + 8), WJ(Wa, 2 * c + 9));
    v.z = packbf(WJ(Wb, 2 * c),     WJ(Wb, 2 * c + 1));
    v.w = packbf(WJ(Wb, 2 * c + 8), WJ(Wb, 2 * c + 9));
#undef WJ
    g_fc1wfrag[(s * 8 + p) * 32 + lane] = v;
}

// ---------------------------------------------------------------------------
// fused conv1+conv2, TWO batch elements per block (r11/r12 winner, unchanged).
// ---------------------------------------------------------------------------
__global__ void __launch_bounds__(256, 2) conv12_kernel(const float* __restrict__ x,
                                                        const float* __restrict__ w1,
                                                        const float* __restrict__ b1,
                                                        const float* __restrict__ b2)
{
    extern __shared__ char smem[];
    uint32_t* sIn0 = (uint32_t*)smem;
    uint32_t* sIn1 = (uint32_t*)(smem + 45968);
    float* sx0 = (float*)(smem + 91936);
    float* sx1 = (float*)(smem + 91936 + 3136);
    float* sw1 = (float*)(smem + 91936 + 6272);
    float* sb1 = (float*)(smem + 91936 + 6272 + 1152);
    float* sb2 = (float*)(smem + 91936 + 6272 + 1152 + 128);

    const int b0 = blockIdx.x * 2;
    const int tid = threadIdx.x;
    const int w = tid >> 5;
    const int lane = tid & 31;

    for (int i = tid; i < 784; i += 256) {
        sx0[i] = x[b0 * 784 + i];
        sx1[i] = x[(b0 + 1) * 784 + i];
    }
    for (int i = tid; i < 288; i += 256) sw1[i] = w1[i];
    if (tid < 32) sb1[tid] = b1[tid];
    for (int i = tid; i < 64; i += 256) sb2[i] = b2[i];
    __syncthreads();

    for (int pp = tid; pp < 1352; pp += 256) {
        const int bb = (pp >= 676);
        const int p = pp - (bb ? 676 : 0);
        const float* sx = bb ? sx1 : sx0;
        uint32_t* dst = (bb ? sIn1 : sIn0) + p * 17;
        const int oy = p / 26, ox = p % 26;
        float in[9];
#pragma unroll
        for (int kh = 0; kh < 3; kh++)
#pragma unroll
            for (int kw = 0; kw < 3; kw++)
                in[kh * 3 + kw] = sx[(oy + kh) * 28 + ox + kw];
#pragma unroll 4
        for (int oc2 = 0; oc2 < 16; oc2++) {
            float va = sb1[2 * oc2], vb = sb1[2 * oc2 + 1];
            const float* wa = sw1 + (2 * oc2) * 9;
#pragma unroll
            for (int j = 0; j < 9; j++) { va += wa[j] * in[j]; vb += wa[9 + j] * in[j]; }
            dst[oc2] = packbf(fmaxf(va, 0.0f), fmaxf(vb, 0.0f));
        }
    }
    __syncthreads();

    const int c = lane & 3;
    const int rl0 = lane >> 2;
    __nv_bfloat16* outB0 = g_poolh + (size_t)b0 * 9216;
    __nv_bfloat16* outB1 = g_poolh + (size_t)(b0 + 1) * 9216;

    for (int t = 0; t < 5; t++) {
        if (t == 4 && w >= 4) break;
        int off0, off1;
        {
            const int qb = t * 32 + w * 4;
            int rl = rl0;
            int quad = qb + (rl >> 2), e = rl & 3;
            int qy = quad / 12, qx = quad - qy * 12;
            off0 = (2 * qy + (e >> 1)) * 26 + 2 * qx + (e & 1);
            rl = rl0 + 8;
            quad = qb + (rl >> 2); e = rl & 3;
            qy = quad / 12; qx = quad - qy * 12;
            off1 = (2 * qy + (e >> 1)) * 26 + 2 * qx + (e & 1);
        }
        const int w0 = off0 * 17 + c;
        const int w1b = off1 * 17 + c;

        float accA[8][4], accE[8][4];
#pragma unroll
        for (int n = 0; n < 8; n++) {
            accA[n][0] = 0.f; accA[n][1] = 0.f; accA[n][2] = 0.f; accA[n][3] = 0.f;
            accE[n][0] = 0.f; accE[n][1] = 0.f; accE[n][2] = 0.f; accE[n][3] = 0.f;
        }

        uint4 bqn[4];
#pragma unroll
        for (int p4 = 0; p4 < 4; p4++) bqn[p4] = g_wfragb[p4 * 32 + lane];

#pragma unroll
        for (int s = 0; s < 18; s++) {
            const int r = s >> 1;
            const int base = ((r / 3) * 26 + (r % 3)) * 17 + (s & 1) * 8;

            uint4 bq[4];
#pragma unroll
            for (int p4 = 0; p4 < 4; p4++) bq[p4] = bqn[p4];
            if (s < 17) {
                const uint4* wfn = g_wfragb + (s + 1) * 128;
#pragma unroll
                for (int p4 = 0; p4 < 4; p4++) bqn[p4] = wfn[p4 * 32 + lane];
            }

            const uint32_t a0 = sIn0[w0 + base];
            const uint32_t a1 = sIn0[w1b + base];
            const uint32_t a2 = sIn0[w0 + base + 4];
            const uint32_t a3 = sIn0[w1b + base + 4];
            const uint32_t e0 = sIn1[w0 + base];
            const uint32_t e1 = sIn1[w1b + base];
            const uint32_t e2 = sIn1[w0 + base + 4];
            const uint32_t e3 = sIn1[w1b + base + 4];

#pragma unroll
            for (int p4 = 0; p4 < 4; p4++) {
                mma_bf16(accA[2 * p4][0], accA[2 * p4][1], accA[2 * p4][2], accA[2 * p4][3],
                         a0, a1, a2, a3, bq[p4].x, bq[p4].y);
                mma_bf16(accA[2 * p4 + 1][0], accA[2 * p4 + 1][1],
                         accA[2 * p4 + 1][2], accA[2 * p4 + 1][3],
                         a0, a1, a2, a3, bq[p4].z, bq[p4].w);
                mma_bf16(accE[2 * p4][0], accE[2 * p4][1], accE[2 * p4][2], accE[2 * p4][3],
                         e0, e1, e2, e3, bq[p4].x, bq[p4].y);
                mma_bf16(accE[2 * p4 + 1][0], accE[2 * p4 + 1][1],
                         accE[2 * p4 + 1][2], accE[2 * p4 + 1][3],
                         e0, e1, e2, e3, bq[p4].z, bq[p4].w);
            }
        }

        const int hh = lane >> 4;
        const int rp = lane & 3;
        const bool writer = ((lane & 12) == 0);
        const int qb = t * 32 + w * 4;
#pragma unroll
        for (int f = 0; f < 2; f++) {
            __nv_bfloat16* outB = f ? outB1 : outB0;
#pragma unroll
            for (int n = 0; n < 8; n++) {
                float v0 = f ? accE[n][0] : accA[n][0];
                float v1 = f ? accE[n][1] : accA[n][1];
                float v2 = f ? accE[n][2] : accA[n][2];
                float v3 = f ? accE[n][3] : accA[n][3];
#pragma unroll
                for (int d = 4; d <= 8; d <<= 1) {
                    v0 = fmaxf(v0, __shfl_xor_sync(0xffffffffu, v0, d));
                    v1 = fmaxf(v1, __shfl_xor_sync(0xffffffffu, v1, d));
                    v2 = fmaxf(v2, __shfl_xor_sync(0xffffffffu, v2, d));
                    v3 = fmaxf(v3, __shfl_xor_sync(0xffffffffu, v3, d));
                }
                if (writer) {
                    const int oc = n * 8 + 2 * rp;
                    const float ba = sb2[oc], bb = sb2[oc + 1];
                    *(uint32_t*)(outB + (qb + hh) * 64 + oc) =
                        packbf(fmaxf(v0 + ba, 0.f), fmaxf(v1 + bb, 0.f));
                    *(uint32_t*)(outB + (qb + 2 + hh) * 64 + oc) =
                        packbf(fmaxf(v2 + ba, 0.f), fmaxf(v3 + bb, 0.f));
                }
            }
        }
    }
}

// ---------------------------------------------------------------------------
// fc1 bf16 tensor-core, K-split 16 (r15 winner) + prefetch distance 2:
// grid (16 Mblocks, 16 ksplits), warp = 16 rows x full N, 36 k-steps.
// ---------------------------------------------------------------------------
__global__ void __launch_bounds__(256) fc1_part_kernel()
{
    const int tid = threadIdx.x;
    const int w = tid >> 5;
    const int lane = tid & 31;
    const int Mb = blockIdx.x;         // 0..15
    const int ks = blockIdx.y;         // 0..15
    const int m0 = Mb * 128 + w * 16;
    const int g = lane >> 2, c = lane & 3;

    float acc[16][4];
#pragma unroll
    for (int f = 0; f < 16; f++) {
        acc[f][0] = 0.f; acc[f][1] = 0.f; acc[f][2] = 0.f; acc[f][3] = 0.f;
    }

    const __nv_bfloat16* A0 = g_poolh + (size_t)(m0 + g) * 9216 + ks * 576 + 2 * c;
    const __nv_bfloat16* A1 = g_poolh + (size_t)(m0 + g + 8) * 9216 + ks * 576 + 2 * c;

    // prefetch pipeline, distance 2
    uint32_t a0 = *(const uint32_t*)(A0);
    uint32_t a1 = *(const uint32_t*)(A1);
    uint32_t a2 = *(const uint32_t*)(A0 + 8);
    uint32_t a3 = *(const uint32_t*)(A1 + 8);
    uint32_t p0 = *(const uint32_t*)(A0 + 16);
    uint32_t p1 = *(const uint32_t*)(A1 + 16);
    uint32_t p2 = *(const uint32_t*)(A0 + 24);
    uint32_t p3 = *(const uint32_t*)(A1 + 24);

#pragma unroll 2
    for (int step = 0; step < 36; step++) {
        uint32_t n0 = 0, n1 = 0, n2 = 0, n3 = 0;
        if (step < 34) {
            const int kn = (step + 2) * 16;
            n0 = *(const uint32_t*)(A0 + kn);
            n1 = *(const uint32_t*)(A1 + kn);
            n2 = *(const uint32_t*)(A0 + kn + 8);
            n3 = *(const uint32_t*)(A1 + kn + 8);
        }
        const uint4* wf = g_fc1wfrag + (size_t)(ks * 36 + step) * 256;
#pragma unroll
        for (int p4 = 0; p4 < 8; p4++) {
            const uint4 bq = wf[p4 * 32 + lane];
            mma_bf16(acc[2 * p4][0], acc[2 * p4][1], acc[2 * p4][2], acc[2 * p4][3],
                     a0, a1, a2, a3, bq.x, bq.y);
            mma_bf16(acc[2 * p4 + 1][0], acc[2 * p4 + 1][1],
                     acc[2 * p4 + 1][2], acc[2 * p4 + 1][3],
                     a0, a1, a2, a3, bq.z, bq.w);
        }
        a0 = p0; a1 = p1; a2 = p2; a3 = p3;
        p0 = n0; p1 = n1; p2 = n2; p3 = n3;
    }

    float* dst = g_part + (size_t)ks * BATCH * 128;
#pragma unroll
    for (int f = 0; f < 16; f++) {
        const int n0i = f * 8 + 2 * c;
        *(float2*)(dst + (size_t)(m0 + g) * 128 + n0i) = make_float2(acc[f][0], acc[f][1]);
        *(float2*)(dst + (size_t)(m0 + g + 8) * 128 + n0i) = make_float2(acc[f][2], acc[f][3]);
    }
}

// ---------------------------------------------------------------------------
// quantum kernel; wire w <-> bit (9-w).  (r12/r13 version; reduce loop 16.)
// ---------------------------------------------------------------------------
__device__ __forceinline__ float2 cmul(float2 a, float2 b) {
    return make_float2(a.x * b.x - a.y * b.y, a.x * b.y + a.y * b.x);
}
__device__ __forceinline__ float2 cadd(float2 a, float2 b) {
    return make_float2(a.x + b.x, a.y + b.y);
}

__global__ void qsim_kernel(const float* __restrict__ fc1b,
                            const float* __restrict__ fc2w,
                            const float* __restrict__ fc2b,
                            const float* __restrict__ theta0,
                            const float* __restrict__ theta_rz,
                            const float* __restrict__ theta_ps,
                            const float* __restrict__ rot_p,
                            float* __restrict__ out)
{
    __shared__ float sh[128];
    __shared__ float sang[10];
    __shared__ float2 svec[10][2];
    __shared__ float2 psi[1024];
    __shared__ float sredk[8][10];
    __shared__ float sev[10];

    const int b = blockIdx.x;
    const int tid = threadIdx.x;
    const int wid = tid >> 5, lane = tid & 31;

    // fc1 K-split reduce + bias + relu
    if (tid < 128) {
        float s = 0.0f;
#pragma unroll
        for (int ks = 0; ks < 16; ks++)
            s += g_part[(size_t)ks * BATCH * 128 + (size_t)b * 128 + tid];
        sh[tid] = fmaxf(s + fc1b[tid], 0.0f);
    }
    __syncthreads();

    if (tid < 10) {
        float z = fc2b[tid];
        const float4* sh4 = (const float4*)sh;
        const float4* wr4 = (const float4*)(fc2w + tid * 128);
        for (int k = 0; k < 32; k++) {
            const float4 hv = sh4[k], wv = wr4[k];
            z += hv.x * wv.x + hv.y * wv.y + hv.z * wv.z + hv.w * wv.w;
        }
        const float a = 6.2831853071795864f / (1.0f + expf(-z));
        sang[tid] = a;

        float alpha = theta0[tid] + a;
        if (tid == 1) alpha += a;
        if (tid == 5) alpha -= 0.78539816339745f;
        const float c = cosf(0.5f * alpha);
        const float s = sinf(0.5f * alpha);
        float2 v0 = make_float2(c, 0.0f);
        float2 v1 = make_float2(0.0f, -s);

        if (tid == 2) {
            const float cy = cosf(0.5f * a), sy = sinf(0.5f * a);
            v0 = make_float2(cy * c, sy * s);
            v1 = make_float2(sy * c, -cy * s);
        } else if (tid == 3) {
            const float2 e = make_float2(cosf(0.5f * a), -sinf(0.5f * a));
            v0 = cmul(v0, e);
            v1 = cmul(v1, make_float2(e.x, -e.y));
        } else if (tid == 4) {
            v1 = make_float2(s, 0.0f);
        } else if (tid == 5) {
            const float r = 0.70710678118654752f;
            v1 = make_float2(s * r, -s * r);
        } else if (tid == 6) {
            const float t = theta_rz[0];
            const float2 e = make_float2(cosf(0.5f * t), -sinf(0.5f * t));
            v0 = cmul(v0, e);
            v1 = cmul(v1, make_float2(e.x, -e.y));
        } else if (tid == 7) {
            const float h0 = 0.5f * (c - s), h1 = 0.5f * (c + s);
            v0 = make_float2(h0, h0);
            v1 = make_float2(h1, -h1);
        }
        svec[tid][0] = v0;
        svec[tid][1] = v1;
    }
    __syncthreads();

    // ---- init with analytic gather of the whole Clifford/phase segment ----
    {
        const float tps = theta_ps[0];
        const float a7 = sang[7];
        const float2 e8 = make_float2(cosf(tps), sinf(tps));
        const float2 e7 = make_float2(cosf(a7), sinf(a7));

#pragma unroll
        for (int ii = 0; ii < 4; ii++) {
            const int i = tid + ii * 256;
            int j = ((i & 18) == 18) ? (i ^ 512) : i;
            if ((j & 32) && (((j >> 3) ^ (j >> 4)) & 1)) j ^= 24;
            if (((j >> 7) ^ (j >> 6)) & 1) j ^= 192;
            const bool cy = (j & 64) != 0;
            const int src = cy ? (j ^ 2) : j;

            float2 p = svec[0][(src >> 9) & 1];
#pragma unroll
            for (int k = 1; k < 10; k++)
                p = cmul(p, svec[k][(src >> (9 - k)) & 1]);
            if (src & 512) p = make_float2(p.y, -p.x);
            if (cy) p = (j & 2) ? make_float2(-p.y, p.x) : make_float2(p.y, -p.x);
            if (i & 2) p = cmul(p, e8);
            if (i & 4) p = cmul(p, e7);
            psi[i] = p;
        }
    }
    __syncthreads();

    // ---- combined Rot(wire4, bit32) x Rot(wire5, bit16) ----
    {
        float m4c, m4s, m4hs, m4hd;
        {
            const float phi = rot_p[0], th = rot_p[1], om = rot_p[2];
            m4c = cosf(0.5f * th); m4s = sinf(0.5f * th);
            m4hs = 0.5f * (phi + om); m4hd = 0.5f * (phi - om);
        }
        const float2 A00 = make_float2(m4c * cosf(m4hs), -m4c * sinf(m4hs));
        const float2 A01 = make_float2(-m4s * cosf(m4hd), -m4s * sinf(m4hd));
        const float2 A10 = make_float2(m4s * cosf(m4hd), -m4s * sinf(m4hd));
        const float2 A11 = make_float2(m4c * cosf(m4hs), m4c * sinf(m4hs));
        float m5c, m5s, m5hs, m5hd;
        {
            const float phi = sang[6], th = sang[7], om = sang[8];
            m5c = cosf(0.5f * th); m5s = sinf(0.5f * th);
            m5hs = 0.5f * (phi + om); m5hd = 0.5f * (phi - om);
        }
        const float2 B00 = make_float2(m5c * cosf(m5hs), -m5c * sinf(m5hs));
        const float2 B01 = make_float2(-m5s * cosf(m5hd), -m5s * sinf(m5hd));
        const float2 B10 = make_float2(m5s * cosf(m5hd), -m5s * sinf(m5hd));
        const float2 B11 = make_float2(m5c * cosf(m5hs), m5c * sinf(m5hs));

        const int g0 = (tid & 15) | ((tid >> 4) << 6);
        float2 t00 = psi[g0];
        float2 t01 = psi[g0 | 32];
        float2 t10 = psi[g0 | 16];
        float2 t11 = psi[g0 | 48];

        float2 u00 = cadd(cmul(A00, t00), cmul(A01, t01));
        float2 u01 = cadd(cmul(A10, t00), cmul(A11, t01));
        float2 u10 = cadd(cmul(A00, t10), cmul(A01, t11));
        float2 u11 = cadd(cmul(A10, t10), cmul(A11, t11));
        psi[g0]      = cadd(cmul(B00, u00), cmul(B01, u10));
        psi[g0 | 32] = cadd(cmul(B00, u01), cmul(B01, u11));
        psi[g0 | 16] = cadd(cmul(B10, u00), cmul(B11, u10));
        psi[g0 | 48] = cadd(cmul(B10, u01), cmul(B11, u11));
    }
    __syncthreads();

    // ---- single-pass expectations ----
    float ev[10];
#pragma unroll
    for (int k = 0; k < 10; k++) ev[k] = 0.0f;
#pragma unroll
    for (int ii = 0; ii < 4; ii++) {
        const int i = tid + ii * 256;
        const float2 a0 = psi[i];
#pragma unroll
        for (int k = 0; k < 10; k++) {
            const int bit = 512 >> k;
            if (!(i & bit)) {
                const float2 a1 = psi[i | bit];
                ev[k] += a0.x * a1.y - a0.y * a1.x;
            }
        }
    }
#pragma unroll
    for (int k = 0; k < 10; k++) {
#pragma unroll
        for (int off = 16; off > 0; off >>= 1)
            ev[k] += __shfl_down_sync(0xffffffffu, ev[k], off);
    }
    if (lane == 0) {
#pragma unroll
        for (int k = 0; k < 10; k++) sredk[wid][k] = ev[k];
    }
    __syncthreads();
    if (tid < 10) {
        float s = 0.0f;
#pragma unroll
        for (int w = 0; w < 8; w++) s += sredk[w][tid];
        sev[tid] = 2.0f * s;
    }
    __syncthreads();

    if (tid == 0) {
        float m = sev[0];
#pragma unroll
        for (int k = 1; k < 10; k++) m = fmaxf(m, sev[k]);
        float ssum = 0.0f;
#pragma unroll
        for (int k = 0; k < 10; k++) ssum += expf(sev[k] - m);
        const float l = logf(ssum);
#pragma unroll
        for (int k = 0; k < 10; k++)
            out[(size_t)b * 10 + k] = sev[k] - m - l;
    }
}

// ---------------------------------------------------------------------------
// launch
// ---------------------------------------------------------------------------
extern "C" void kernel_launch(void* const* d_in, const int* in_sizes, int n_in,
                              void* d_out, int out_size)
{
    const float* x        = (const float*)d_in[0];
    const float* conv1_w  = (const float*)d_in[1];
    const float* conv1_b  = (const float*)d_in[2];
    const float* conv2_w  = (const float*)d_in[3];
    const float* conv2_b  = (const float*)d_in[4];
    const float* fc1_w    = (const float*)d_in[5];
    const float* fc1_b    = (const float*)d_in[6];
    const float* fc2_w    = (const float*)d_in[7];
    const float* fc2_b    = (const float*)d_in[8];
    const float* theta0   = (const float*)d_in[9];
    const float* theta_rz = (const float*)d_in[10];
    const float* theta_ps = (const float*)d_in[11];
    const float* rot_p    = (const float*)d_in[12];
    float* out = (float*)d_out;

    // 2*45968 + 2*3136 + 1152 + 128 + 256 = 99744 B
    const int conv_smem = 99744;
    cudaFuncSetAttribute(conv12_kernel, cudaFuncAttributeMaxDynamicSharedMemorySize,
                         conv_smem);

    prep_wfrag_kernel<<<18, 128>>>(conv2_w);
    prep_fc1frag_kernel<<<576, 256>>>(fc1_w);
    conv12_kernel<<<BATCH / 2, 256, conv_smem>>>(x, conv1_w, conv1_b, conv2_b);
    fc1_part_kernel<<<dim3(16, 16), 256>>>();
    qsim_kernel<<<BATCH, 256>>>(fc1_b, fc2_w, fc2_b, theta0, theta_rz, theta_ps, rot_p, out);
}